// round 16
// baseline (speedup 1.0000x reference)
#include <cuda_runtime.h>
#include <math.h>

#define BATCHN 2048
#define SEQN   512
#define INPN   128
#define HIDN   256
#define OUTN   64
#define KTOT   384
#define NKT    24            // k-tiles of 16
#define ROWS   16
#define NPROD  128
#define NCONS  20
#define GRIDN  (NPROD + NCONS)   // 148 = one CTA per SM
#define NTHR   512
#define AKS    136           // As per-ktile stride in u32 (128 + 8 pad)
#define VSTR   258           // vfin row stride (floats)
#define SHP    66            // consumer sh row pad (floats)
#define NTILE  (32 * SEQN)   // (2048/64) row-groups x 512 timesteps
#define FEPS   1e-8f

typedef unsigned long long u64t;
typedef unsigned short u16t;

// weight fragments, lambda-folded, bf16 hi/lo planes, mma-fragment-major
__device__ u64t  g_WB[2 * NKT * 32 * 32];
__device__ float g_H[(size_t)BATCHN * SEQN * HIDN];   // h history (1 GB scratch)
__device__ int      g_prog[NPROD];
__device__ unsigned g_ticket;

__device__ __forceinline__ u64t dup2(float a) {
    u64t r; asm("mov.b64 %0, {%1, %1};" : "=l"(r) : "f"(a)); return r;
}
__device__ __forceinline__ void ffma2(u64t& d, u64t a, u64t b) {
    asm("fma.rn.f32x2 %0, %1, %2, %0;" : "+l"(d) : "l"(a), "l"(b));
}
__device__ __forceinline__ float lo2(u64t v) { return __uint_as_float((unsigned)v); }
__device__ __forceinline__ float hi2(u64t v) { return __uint_as_float((unsigned)(v >> 32)); }

__device__ __forceinline__ u16t bf16h(float v) {
    u16t h; asm("cvt.rn.bf16.f32 %0, %1;" : "=h"(h) : "f"(v)); return h;
}
__device__ __forceinline__ float bf16f(u16t h) {
    return __uint_as_float(((unsigned)h) << 16);
}
__device__ __forceinline__ void mma16816(float* d, uint4 a, u64t b) {
    unsigned b0 = (unsigned)b, b1 = (unsigned)(b >> 32);
    asm volatile(
        "mma.sync.aligned.m16n8k16.row.col.f32.bf16.bf16.f32 "
        "{%0,%1,%2,%3},{%4,%5,%6,%7},{%8,%9},{%0,%1,%2,%3};"
        : "+f"(d[0]), "+f"(d[1]), "+f"(d[2]), "+f"(d[3])
        : "r"(a.x), "r"(a.y), "r"(a.z), "r"(a.w), "r"(b0), "r"(b1));
}
__device__ __forceinline__ int ld_acq(const int* p) {
    int v; asm volatile("ld.global.acquire.gpu.b32 %0, [%1];" : "=r"(v) : "l"(p)); return v;
}
__device__ __forceinline__ void st_rel(int* p, int v) {
    asm volatile("st.global.release.gpu.b32 [%0], %1;" :: "l"(p), "r"(v) : "memory");
}

__device__ __forceinline__ float wfull(int k, int n,
        const float* Win, const float* Wrec, const float* li, const float* lr) {
    return (k < HIDN) ? lr[n] * Wrec[k * HIDN + n]
                      : li[n] * Win[(k - HIDN) * HIDN + n];
}

__global__ void prep_kernel(const float* __restrict__ Win, const float* __restrict__ Wrec,
                            const float* __restrict__ li,  const float* __restrict__ lr) {
    int gid = blockIdx.x * blockDim.x + threadIdx.x;
    int kt = gid >> 10, rem = gid & 1023;
    int nt = rem >> 5, l = rem & 31;
    if (kt >= NKT) return;
    int k0 = kt * 16 + (l & 3) * 2;
    int n  = nt * 8 + (l >> 2);
    float e[4];
    e[0] = wfull(k0, n, Win, Wrec, li, lr);
    e[1] = wfull(k0 + 1, n, Win, Wrec, li, lr);
    e[2] = wfull(k0 + 8, n, Win, Wrec, li, lr);
    e[3] = wfull(k0 + 9, n, Win, Wrec, li, lr);
    u16t hi[4], lo[4];
#pragma unroll
    for (int i = 0; i < 4; ++i) {
        hi[i] = bf16h(e[i]);
        lo[i] = bf16h(e[i] - bf16f(hi[i]));
    }
    u64t vhi = (u64t)((unsigned)hi[0] | ((unsigned)hi[1] << 16))
             | ((u64t)((unsigned)hi[2] | ((unsigned)hi[3] << 16)) << 32);
    u64t vlo = (u64t)((unsigned)lo[0] | ((unsigned)lo[1] << 16))
             | ((u64t)((unsigned)lo[2] | ((unsigned)lo[3] << 16)) << 32);
    int base = (kt * 32 + nt) * 32 + l;
    g_WB[base] = vhi;
    g_WB[NKT * 32 * 32 + base] = vlo;
}

__global__ void reset_kernel() {
    if (threadIdx.x < NPROD) g_prog[threadIdx.x] = 0;
    if (threadIdx.x == 0)    g_ticket = 0u;
}

// Consumer: out tiles of 64 rows x 64 cols; sh needs 256*SHP floats (67.6 KB)
__device__ void consume_tiles(float* sh, const float* __restrict__ Wout,
                              float sz, float* __restrict__ outp) {
    __shared__ unsigned s_n;
    const int tid = threadIdx.x;
    const int c = tid & 63, rg = tid >> 6;
    for (;;) {
        if (tid == 0) s_n = atomicAdd(&g_ticket, 1u);
        __syncthreads();
        unsigned n = s_n;
        if (n >= NTILE) { __syncthreads(); return; }
        int t = n >> 5, mg = n & 31;

        if (tid < 4) {
            const int* fp = &g_prog[mg * 4 + tid];
            while (ld_acq(fp) < t + 1) __nanosleep(256);
        }
        __syncthreads();

        for (int idx = tid; idx < 64 * HIDN; idx += NTHR) {
            int r = idx >> 8, j = idx & 255;
            sh[j * SHP + r] = g_H[((size_t)(mg * 64 + r) * SEQN + t) * HIDN + j];
        }
        __syncthreads();

        u64t acc[4] = {0ull, 0ull, 0ull, 0ull};
        const float* wo = Wout + c;
#pragma unroll 4
        for (int j = 0; j < HIDN; ++j) {
            u64t b = dup2(wo[j * OUTN]);
            const float* hp = sh + j * SHP + rg * 8;
            u64t h0 = *(const u64t*)(hp);
            u64t h1 = *(const u64t*)(hp + 2);
            u64t h2 = *(const u64t*)(hp + 4);
            u64t h3 = *(const u64t*)(hp + 6);
            ffma2(acc[0], h0, b); ffma2(acc[1], h1, b);
            ffma2(acc[2], h2, b); ffma2(acc[3], h3, b);
        }
#pragma unroll
        for (int p = 0; p < 4; ++p) {
            int br = mg * 64 + rg * 8 + 2 * p;
            outp[((size_t)br * SEQN + t) * OUTN + c]       = sz * lo2(acc[p]);
            outp[((size_t)(br + 1) * SEQN + t) * OUTN + c] = sz * hi2(acc[p]);
        }
        __syncthreads();
    }
}

__global__ void __launch_bounds__(NTHR, 1) nlnn_fused(
    const float* __restrict__ x,
    const float* __restrict__ h_init,
    const float* __restrict__ alpha_raw,
    const float* __restrict__ Wout,
    const float* __restrict__ s_z_p,
    float* __restrict__ outp,
    float* __restrict__ hfin)
{
    // dynamic shared buffer (16B-aligned), sized for the larger role:
    //  producer: As (2*NKT*AKS u32 = 52.2KB... actually 26.1KB) + vfin (16.5KB)
    //  consumer: sh (256*SHP floats = 67.6KB)   <-- sizing role
    extern __shared__ unsigned smbuf[];
    const int tid = threadIdx.x;
    const float sz = s_z_p[0];

    if (blockIdx.x >= NPROD) {
        consume_tiles((float*)smbuf, Wout, sz, outp);
        return;
    }

    unsigned* As  = smbuf;
    float* vfin   = (float*)(smbuf + 2 * NKT * AKS);
    u16t* As16    = (u16t*)As;

    const int b0   = blockIdx.x * ROWS;
    const int w    = tid >> 5, lane = tid & 31;
    const int nt0  = 2 * w;
    const int la4  = lane * 4;

    const int k15   = lane & 15;
    const int tl    = (w & 7) * 4 + ((k15 & 7) >> 1);
    const int aidx  = ((w >> 3) & 1) + ((k15 >> 3) << 1);
    const int aoff  = tl * 8 + aidx * 2 + (k15 & 1);
    const int ktb   = lane >> 4;

    float hh[8], al[8];
#pragma unroll
    for (int i = 0; i < 8; ++i) {
        int j = lane + 32 * i;
        hh[i] = h_init[(size_t)(b0 + w) * HIDN + j];
        al[i] = 1.0f / (1.0f + expf(-alpha_raw[j]));
        int kt = ktb + 2 * i;
        u16t bh = bf16h(hh[i]);
        u16t bl = bf16h(hh[i] - bf16f(bh));
        As16[kt * (2 * AKS) + aoff] = bh;
        As16[(NKT + kt) * (2 * AKS) + aoff] = bl;
    }
    float xr[4];
#pragma unroll
    for (int i = 0; i < 4; ++i) {
        float xv = x[(size_t)(b0 + w) * SEQN * INPN + lane + 32 * i];
        int kt = 16 + ktb + 2 * i;
        u16t bh = bf16h(xv);
        u16t bl = bf16h(xv - bf16f(bh));
        As16[kt * (2 * AKS) + aoff] = bh;
        As16[(NKT + kt) * (2 * AKS) + aoff] = bl;
        xr[i] = x[((size_t)(b0 + w) * SEQN + 1) * INPN + lane + 32 * i];
    }
    __syncthreads();

    const u64t* __restrict__ WB = g_WB;

    for (int t = 0; t < SEQN; ++t) {
        float d0[4] = {0.f, 0.f, 0.f, 0.f};
        float d1[4] = {0.f, 0.f, 0.f, 0.f};
#pragma unroll
        for (int kt = 0; kt < NKT; ++kt) {
            uint4 ah  = *(const uint4*)(As + kt * AKS + la4);
            uint4 alo = *(const uint4*)(As + (NKT + kt) * AKS + la4);
            int bi = (kt * 32 + nt0) * 32 + lane;
            u64t bh0 = WB[bi];
            u64t bl0 = WB[NKT * 1024 + bi];
            u64t bh1 = WB[bi + 32];
            u64t bl1 = WB[NKT * 1024 + bi + 32];
            mma16816(d0, ah, bh0);
            mma16816(d0, alo, bh0);
            mma16816(d0, ah, bl0);
            mma16816(d1, ah, bh1);
            mma16816(d1, alo, bh1);
            mma16816(d1, ah, bl1);
        }
        {
            int gr = lane >> 2;
            float* vf = vfin + gr * VSTR + nt0 * 8 + (lane & 3) * 2;
            *(float2*)(vf)                = make_float2(d0[0], d0[1]);
            *(float2*)(vf + 8 * VSTR)     = make_float2(d0[2], d0[3]);
            *(float2*)(vf + 8)            = make_float2(d1[0], d1[1]);
            *(float2*)(vf + 8 * VSTR + 8) = make_float2(d1[2], d1[3]);
        }
        __syncthreads();                   // S2: vfin ready, As reads done

        float vv[8], ssq = 0.f, hsq = 0.f, dtr = 0.f;
#pragma unroll
        for (int i = 0; i < 8; ++i) {
            float s = vfin[w * VSTR + lane + 32 * i];
            vv[i] = s;
            ssq = fmaf(s, s, ssq);
            hsq = fmaf(hh[i], hh[i], hsq);
            dtr = fmaf(hh[i], s, dtr);
        }
#pragma unroll
        for (int d = 16; d > 0; d >>= 1) {
            ssq += __shfl_xor_sync(0xffffffffu, ssq, d);
            hsq += __shfl_xor_sync(0xffffffffu, hsq, d);
            dtr += __shfl_xor_sync(0xffffffffu, dtr, d);
        }
        float ninv = 1.0f / (sqrtf(ssq) + FEPS);
        float hinv = 1.0f / (sqrtf(hsq) + FEPS);
        float dot  = dtr * ninv * hinv;
        dot = fminf(fmaxf(dot, -1.0f + FEPS), 1.0f - FEPS);
        float theta  = acosf(dot);
        float st     = __sinf(theta);
        float inv_st = 1.0f / (st + FEPS);
        bool  mask   = (st > FEPS);

        float res[8], rsq = 0.f;
#pragma unroll
        for (int i = 0; i < 8; ++i) {
            float hn = vv[i] * ninv;
            float ht = hh[i] * hinv;
            float ct = __sinf((1.0f - al[i]) * theta) * inv_st;
            float cn = __sinf(al[i] * theta) * inv_st;
            float r  = fmaf(ct, ht, cn * hn);
            r = mask ? r : hn;
            res[i] = r;
            rsq = fmaf(r, r, rsq);
        }
#pragma unroll
        for (int d = 16; d > 0; d >>= 1)
            rsq += __shfl_xor_sync(0xffffffffu, rsq, d);
        float rinv = 1.0f / (sqrtf(rsq) + FEPS);

        float* hrow = g_H + ((size_t)(b0 + w) * SEQN + t) * HIDN;
#pragma unroll
        for (int i = 0; i < 8; ++i) {
            float h = res[i] * rinv;
            hh[i] = h;
            hrow[lane + 32 * i] = h;
            int kt = ktb + 2 * i;
            u16t bh = bf16h(h);
            u16t bl = bf16h(h - bf16f(bh));
            As16[kt * (2 * AKS) + aoff] = bh;
            As16[(NKT + kt) * (2 * AKS) + aoff] = bl;
        }
        {
            int tt = (t + 2 < SEQN) ? t + 2 : SEQN - 1;
#pragma unroll
            for (int i = 0; i < 4; ++i) {
                int kt = 16 + ktb + 2 * i;
                u16t bh = bf16h(xr[i]);
                u16t bl = bf16h(xr[i] - bf16f(bh));
                As16[kt * (2 * AKS) + aoff] = bh;
                As16[(NKT + kt) * (2 * AKS) + aoff] = bl;
                xr[i] = x[((size_t)(b0 + w) * SEQN + tt) * INPN + lane + 32 * i];
            }
        }
        __syncthreads();                   // S1: As ready for t+1

        // publish progress every 8 steps: release STORE, no fence -> no CCTL.IVALL
        if ((t & 7) == 7 && tid == 0)
            st_rel(&g_prog[blockIdx.x], t + 1);
    }

    if (hfin) {
#pragma unroll
        for (int i = 0; i < 8; ++i)
            hfin[(size_t)(b0 + w) * HIDN + lane + 32 * i] = hh[i];
    }

    __syncthreads();
    consume_tiles((float*)smbuf, Wout, sz, outp);   // role switch
}

extern "C" void kernel_launch(void* const* d_in, const int* in_sizes, int n_in,
                              void* d_out, int out_size) {
    const float* x      = (const float*)d_in[0];
    const float* h_init = (const float*)d_in[1];
    const float* Win    = (const float*)d_in[2];
    const float* Wrec   = (const float*)d_in[3];
    const float* Wout   = (const float*)d_in[4];
    const float* li     = (const float*)d_in[5];
    const float* lr     = (const float*)d_in[6];
    const float* sz     = (const float*)d_in[7];
    const float* ar     = (const float*)d_in[8];

    float* outp = (float*)d_out;
    long long main_elems = (long long)BATCHN * SEQN * OUTN;
    float* hfin = nullptr;
    if ((long long)out_size >= main_elems + (long long)BATCHN * HIDN)
        hfin = outp + main_elems;

    int smem_prod = (2 * NKT * AKS + ROWS * VSTR) * (int)sizeof(unsigned);  // 42.6 KB
    int smem_cons = (HIDN * SHP) * (int)sizeof(float);                      // 67.6 KB
    int smem = smem_prod > smem_cons ? smem_prod : smem_cons;
    cudaFuncSetAttribute(nlnn_fused, cudaFuncAttributeMaxDynamicSharedMemorySize, smem);

    prep_kernel<<<96, 256>>>(Win, Wrec, li, lr);
    nlnn_fused<<<GRIDN, NTHR, smem>>>(x, h_init, ar, Wout, sz, outp, hfin);
    reset_kernel<<<1, 256>>>();   // clear flags/ticket for next graph replay
    reset_kernel<<<1, 256>>>();   // pad
}

// round 17
// speedup vs baseline: 1.2063x; 1.2063x over previous
#include <cuda_runtime.h>
#include <math.h>

#define BATCHN 2048
#define SEQN   512
#define INPN   128
#define HIDN   256
#define OUTN   64
#define KTOT   384
#define NKT    24            // k-tiles of 16
#define NCKT   11            // k-tiles cached in smem (both planes): 180.2 KB
#define ROWS   16
#define NTHR   512
#define AKS    136           // As per-ktile stride in u32 (128 + 8 pad)
#define VSTR   258           // vfin row stride (floats)
#define FEPS   1e-8f

typedef unsigned long long u64t;
typedef unsigned short u16t;

// weight fragments, lambda-folded, bf16 hi/lo planes, mma-fragment-major:
// hi plane at [kt*1024 + nt*32 + lane], lo plane at +NKT*1024
__device__ u64t  g_WB[2 * NKT * 32 * 32];
__device__ float g_H[(size_t)BATCHN * SEQN * HIDN];   // h history (1 GB scratch)

__device__ __forceinline__ u64t dup2(float a) {
    u64t r; asm("mov.b64 %0, {%1, %1};" : "=l"(r) : "f"(a)); return r;
}
__device__ __forceinline__ void ffma2(u64t& d, u64t a, u64t b) {
    asm("fma.rn.f32x2 %0, %1, %2, %0;" : "+l"(d) : "l"(a), "l"(b));
}
__device__ __forceinline__ float lo2(u64t v) { return __uint_as_float((unsigned)v); }
__device__ __forceinline__ float hi2(u64t v) { return __uint_as_float((unsigned)(v >> 32)); }

__device__ __forceinline__ u16t bf16h(float v) {
    u16t h; asm("cvt.rn.bf16.f32 %0, %1;" : "=h"(h) : "f"(v)); return h;
}
__device__ __forceinline__ float bf16f(u16t h) {
    return __uint_as_float(((unsigned)h) << 16);
}
__device__ __forceinline__ void mma16816(float* d, uint4 a, u64t b) {
    unsigned b0 = (unsigned)b, b1 = (unsigned)(b >> 32);
    asm volatile(
        "mma.sync.aligned.m16n8k16.row.col.f32.bf16.bf16.f32 "
        "{%0,%1,%2,%3},{%4,%5,%6,%7},{%8,%9},{%0,%1,%2,%3};"
        : "+f"(d[0]), "+f"(d[1]), "+f"(d[2]), "+f"(d[3])
        : "r"(a.x), "r"(a.y), "r"(a.z), "r"(a.w), "r"(b0), "r"(b1));
}

__device__ __forceinline__ float wfull(int k, int n,
        const float* Win, const float* Wrec, const float* li, const float* lr) {
    return (k < HIDN) ? lr[n] * Wrec[k * HIDN + n]
                      : li[n] * Win[(k - HIDN) * HIDN + n];
}

__global__ void prep_kernel(const float* __restrict__ Win, const float* __restrict__ Wrec,
                            const float* __restrict__ li,  const float* __restrict__ lr) {
    int gid = blockIdx.x * blockDim.x + threadIdx.x;
    int kt = gid >> 10, rem = gid & 1023;
    int nt = rem >> 5, l = rem & 31;
    if (kt >= NKT) return;
    int k0 = kt * 16 + (l & 3) * 2;
    int n  = nt * 8 + (l >> 2);
    float e[4];
    e[0] = wfull(k0, n, Win, Wrec, li, lr);
    e[1] = wfull(k0 + 1, n, Win, Wrec, li, lr);
    e[2] = wfull(k0 + 8, n, Win, Wrec, li, lr);
    e[3] = wfull(k0 + 9, n, Win, Wrec, li, lr);
    u16t hi[4], lo[4];
#pragma unroll
    for (int i = 0; i < 4; ++i) {
        hi[i] = bf16h(e[i]);
        lo[i] = bf16h(e[i] - bf16f(hi[i]));
    }
    u64t vhi = (u64t)((unsigned)hi[0] | ((unsigned)hi[1] << 16))
             | ((u64t)((unsigned)hi[2] | ((unsigned)hi[3] << 16)) << 32);
    u64t vlo = (u64t)((unsigned)lo[0] | ((unsigned)lo[1] << 16))
             | ((u64t)((unsigned)lo[2] | ((unsigned)lo[3] << 16)) << 32);
    int base = (kt * 32 + nt) * 32 + l;
    g_WB[base] = vhi;
    g_WB[NKT * 32 * 32 + base] = vlo;
}

__global__ void __launch_bounds__(NTHR, 1) nlnn_main(
    const float* __restrict__ x,         // [B,S,128]
    const float* __restrict__ h_init,    // [B,256]
    const float* __restrict__ alpha_raw, // [256]
    float* __restrict__ hfin)
{
    // dynamic smem: Wc[NCKT*2*1024 u64] (180.2KB) | As[2*NKT*AKS u32] (26.1KB)
    //               | vfin[16*VSTR f] (16.5KB)  = 222.8 KB total
    extern __shared__ u64t smem8[];
    u64t*     Wc   = smem8;                                  // cached W k-tiles
    unsigned* As   = (unsigned*)(smem8 + NCKT * 2 * 1024);
    float*    vfin = (float*)(As + 2 * NKT * AKS);
    u16t*     As16 = (u16t*)As;

    const int tid  = threadIdx.x;
    const int b0   = blockIdx.x * ROWS;
    const int w    = tid >> 5, lane = tid & 31;   // warp w <-> batch row w & n-slice w
    const int nt0  = 2 * w;
    const int la4  = lane * 4;

    // one-time W cache fill: kt<NCKT, hi -> Wc[kt*2*1024 ..], lo -> +1024
    for (int i = tid; i < NCKT * 1024; i += NTHR) {
        int kt = i >> 10, r = i & 1023;
        Wc[kt * 2048 + r]        = g_WB[kt * 1024 + r];
        Wc[kt * 2048 + 1024 + r] = g_WB[NKT * 1024 + kt * 1024 + r];
    }

    const int k15   = lane & 15;
    const int tl    = (w & 7) * 4 + ((k15 & 7) >> 1);
    const int aidx  = ((w >> 3) & 1) + ((k15 >> 3) << 1);
    const int aoff  = tl * 8 + aidx * 2 + (k15 & 1);
    const int ktb   = lane >> 4;

    float hh[8], al[8];
#pragma unroll
    for (int i = 0; i < 8; ++i) {
        int j = lane + 32 * i;
        hh[i] = h_init[(size_t)(b0 + w) * HIDN + j];
        al[i] = 1.0f / (1.0f + expf(-alpha_raw[j]));
        int kt = ktb + 2 * i;
        u16t bh = bf16h(hh[i]);
        u16t bl = bf16h(hh[i] - bf16f(bh));
        As16[kt * (2 * AKS) + aoff] = bh;
        As16[(NKT + kt) * (2 * AKS) + aoff] = bl;
    }
    float xr[4];
#pragma unroll
    for (int i = 0; i < 4; ++i) {
        float xv = x[(size_t)(b0 + w) * SEQN * INPN + lane + 32 * i];
        int kt = 16 + ktb + 2 * i;
        u16t bh = bf16h(xv);
        u16t bl = bf16h(xv - bf16f(bh));
        As16[kt * (2 * AKS) + aoff] = bh;
        As16[(NKT + kt) * (2 * AKS) + aoff] = bl;
        xr[i] = x[((size_t)(b0 + w) * SEQN + 1) * INPN + lane + 32 * i];
    }
    __syncthreads();

    const u64t* __restrict__ WB = g_WB;

    for (int t = 0; t < SEQN; ++t) {
        float d0[4] = {0.f, 0.f, 0.f, 0.f};
        float d1[4] = {0.f, 0.f, 0.f, 0.f};
#pragma unroll
        for (int kt = 0; kt < NKT; ++kt) {
            uint4 ah  = *(const uint4*)(As + kt * AKS + la4);
            uint4 alo = *(const uint4*)(As + (NKT + kt) * AKS + la4);
            u64t bh0, bl0, bh1, bl1;
            if (kt < NCKT) {                       // compile-time split
                const u64t* wb = Wc + kt * 2048 + nt0 * 32 + lane;
                bh0 = wb[0];    bh1 = wb[32];
                bl0 = wb[1024]; bl1 = wb[1024 + 32];
            } else {
                int bi = (kt * 32 + nt0) * 32 + lane;
                bh0 = WB[bi];              bh1 = WB[bi + 32];
                bl0 = WB[NKT * 1024 + bi]; bl1 = WB[NKT * 1024 + bi + 32];
            }
            mma16816(d0, ah, bh0);
            mma16816(d0, alo, bh0);
            mma16816(d0, ah, bl0);
            mma16816(d1, ah, bh1);
            mma16816(d1, alo, bh1);
            mma16816(d1, ah, bl1);
        }
        {
            int gr = lane >> 2;
            float* vf = vfin + gr * VSTR + nt0 * 8 + (lane & 3) * 2;
            *(float2*)(vf)                = make_float2(d0[0], d0[1]);
            *(float2*)(vf + 8 * VSTR)     = make_float2(d0[2], d0[3]);
            *(float2*)(vf + 8)            = make_float2(d1[0], d1[1]);
            *(float2*)(vf + 8 * VSTR + 8) = make_float2(d1[2], d1[3]);
        }
        __syncthreads();                   // S2: vfin ready, As reads done

        float vv[8], ssq = 0.f, hsq = 0.f, dtr = 0.f;
#pragma unroll
        for (int i = 0; i < 8; ++i) {
            float s = vfin[w * VSTR + lane + 32 * i];
            vv[i] = s;
            ssq = fmaf(s, s, ssq);
            hsq = fmaf(hh[i], hh[i], hsq);
            dtr = fmaf(hh[i], s, dtr);
        }
#pragma unroll
        for (int d = 16; d > 0; d >>= 1) {
            ssq += __shfl_xor_sync(0xffffffffu, ssq, d);
            hsq += __shfl_xor_sync(0xffffffffu, hsq, d);
            dtr += __shfl_xor_sync(0xffffffffu, dtr, d);
        }
        float ninv = 1.0f / (sqrtf(ssq) + FEPS);
        float hinv = 1.0f / (sqrtf(hsq) + FEPS);
        float dot  = dtr * ninv * hinv;
        dot = fminf(fmaxf(dot, -1.0f + FEPS), 1.0f - FEPS);
        float theta  = acosf(dot);
        float st     = __sinf(theta);
        float inv_st = 1.0f / (st + FEPS);
        bool  mask   = (st > FEPS);

        float res[8], rsq = 0.f;
#pragma unroll
        for (int i = 0; i < 8; ++i) {
            float hn = vv[i] * ninv;
            float ht = hh[i] * hinv;
            float ct = __sinf((1.0f - al[i]) * theta) * inv_st;
            float cn = __sinf(al[i] * theta) * inv_st;
            float r  = fmaf(ct, ht, cn * hn);
            r = mask ? r : hn;
            res[i] = r;
            rsq = fmaf(r, r, rsq);
        }
#pragma unroll
        for (int d = 16; d > 0; d >>= 1)
            rsq += __shfl_xor_sync(0xffffffffu, rsq, d);
        float rinv = 1.0f / (sqrtf(rsq) + FEPS);

        float* hrow = g_H + ((size_t)(b0 + w) * SEQN + t) * HIDN;
#pragma unroll
        for (int i = 0; i < 8; ++i) {
            float h = res[i] * rinv;
            hh[i] = h;
            hrow[lane + 32 * i] = h;
            int kt = ktb + 2 * i;
            u16t bh = bf16h(h);
            u16t bl = bf16h(h - bf16f(bh));
            As16[kt * (2 * AKS) + aoff] = bh;
            As16[(NKT + kt) * (2 * AKS) + aoff] = bl;
        }
        {
            int tt = (t + 2 < SEQN) ? t + 2 : SEQN - 1;
#pragma unroll
            for (int i = 0; i < 4; ++i) {
                int kt = 16 + ktb + 2 * i;
                u16t bh = bf16h(xr[i]);
                u16t bl = bf16h(xr[i] - bf16f(bh));
                As16[kt * (2 * AKS) + aoff] = bh;
                As16[(NKT + kt) * (2 * AKS) + aoff] = bl;
                xr[i] = x[((size_t)(b0 + w) * SEQN + tt) * INPN + lane + 32 * i];
            }
        }
        __syncthreads();                   // S1: As ready for t+1
    }

    if (hfin) {
#pragma unroll
        for (int i = 0; i < 8; ++i)
            hfin[(size_t)(b0 + w) * HIDN + lane + 32 * i] = hh[i];
    }
}

// out[row][c] = s_z * sum_j H[row][j]*Wout[j][c]  (fp32, unchanged from R14)
#define OB_ROWS 64
#define HSTR    68
__global__ void __launch_bounds__(256, 2) nlnn_out(
    const float* __restrict__ Wout, const float* __restrict__ s_z_p,
    float* __restrict__ outp)
{
    extern __shared__ float sh[];                     // [256][HSTR]
    const int tid = threadIdx.x;
    const size_t row0 = (size_t)blockIdx.x * OB_ROWS;

#pragma unroll 8
    for (int i = 0; i < OB_ROWS; ++i)
        sh[tid * HSTR + i] = g_H[(row0 + i) * HIDN + tid];
    __syncthreads();

    const int c = tid & 63, rb = (tid >> 6) * 16;
    const float sz = s_z_p[0];

    u64t acc[8];
#pragma unroll
    for (int p = 0; p < 8; ++p) acc[p] = 0ull;

#pragma unroll 4
    for (int j = 0; j < HIDN; ++j) {
        u64t b = dup2(Wout[j * OUTN + c]);
        const float* hp = sh + j * HSTR + rb;
        ulonglong2 hA = *(const ulonglong2*)(hp);
        ulonglong2 hB = *(const ulonglong2*)(hp + 4);
        ulonglong2 hC = *(const ulonglong2*)(hp + 8);
        ulonglong2 hD = *(const ulonglong2*)(hp + 12);
        ffma2(acc[0], hA.x, b); ffma2(acc[1], hA.y, b);
        ffma2(acc[2], hB.x, b); ffma2(acc[3], hB.y, b);
        ffma2(acc[4], hC.x, b); ffma2(acc[5], hC.y, b);
        ffma2(acc[6], hD.x, b); ffma2(acc[7], hD.y, b);
    }
#pragma unroll
    for (int p = 0; p < 8; ++p) {
        size_t r = row0 + rb + 2 * p;
        outp[r * OUTN + c]       = sz * lo2(acc[p]);
        outp[(r + 1) * OUTN + c] = sz * hi2(acc[p]);
    }
}

extern "C" void kernel_launch(void* const* d_in, const int* in_sizes, int n_in,
                              void* d_out, int out_size) {
    const float* x      = (const float*)d_in[0];
    const float* h_init = (const float*)d_in[1];
    const float* Win    = (const float*)d_in[2];
    const float* Wrec   = (const float*)d_in[3];
    const float* Wout   = (const float*)d_in[4];
    const float* li     = (const float*)d_in[5];
    const float* lr     = (const float*)d_in[6];
    const float* sz     = (const float*)d_in[7];
    const float* ar     = (const float*)d_in[8];

    float* outp = (float*)d_out;
    long long main_elems = (long long)BATCHN * SEQN * OUTN;
    float* hfin = nullptr;
    if ((long long)out_size >= main_elems + (long long)BATCHN * HIDN)
        hfin = outp + main_elems;

    int smem_main = NCKT * 2 * 1024 * 8 + 2 * NKT * AKS * 4 + ROWS * VSTR * 4; // 222,848 B
    int smem_out  = (HIDN * HSTR) * (int)sizeof(float);
    cudaFuncSetAttribute(nlnn_main, cudaFuncAttributeMaxDynamicSharedMemorySize, smem_main);
    cudaFuncSetAttribute(nlnn_out,  cudaFuncAttributeMaxDynamicSharedMemorySize, smem_out);

    prep_kernel<<<96, 256>>>(Win, Wrec, li, lr);
    nlnn_main<<<BATCHN / ROWS, NTHR, smem_main>>>(x, h_init, ar, hfin);
    nlnn_out<<<(BATCHN * SEQN) / OB_ROWS, 256, smem_out>>>(Wout, sz, outp);
}